// round 1
// baseline (speedup 1.0000x reference)
#include <cuda_runtime.h>
#include <math.h>

#define SLOPE 0.2f

// Shapes are fixed by the problem: B=8, N=2048, D=128.
// Scratch (device globals; no allocations anywhere).
__device__ float g_h[8 * 2048 * 128];        // h = x @ W
__device__ float g_ssrc[8 * 2048];           // h @ a_src
__device__ float g_sdst[8 * 2048];           // h @ a_dst
__device__ float g_v[8 * 2048];              // sorted s_dst per batch
__device__ int   g_perm[8 * 2048];           // sorted order -> original j
__device__ float g_w1[8 * 2048];             // exp(v_r)
__device__ float g_w02[8 * 2048];            // exp(0.2 v_r)
__device__ float g_suf1[8 * 2049 * 128];     // suffix sums of e^{v} * h
__device__ float g_pre02[8 * 2049 * 128];    // prefix sums of e^{0.2v} * h
__device__ float g_sufD1[8 * 2049];          // suffix sums of e^{v}
__device__ float g_preD02[8 * 2049];         // prefix sums of e^{0.2v}

// ---------------------------------------------------------------------------
// K1: h = x @ W   (M=16384, N=128, K=128) fp32 tiled
// ---------------------------------------------------------------------------
__global__ __launch_bounds__(256) void k1_xw(const float* __restrict__ x,
                                             const float* __restrict__ W) {
    __shared__ float xs[64][33];
    __shared__ float Ws[32][128];
    const int tid = threadIdx.x;
    const int row0 = blockIdx.x * 64;
    const int ig = tid >> 4, og = tid & 15;
    const int iBase = ig * 4, oBase = og * 8;
    float acc[4][8];
#pragma unroll
    for (int a = 0; a < 4; a++)
#pragma unroll
        for (int c = 0; c < 8; c++) acc[a][c] = 0.f;

    const int seg = tid & 7, r = tid >> 3;  // for x-tile loads
    for (int k0 = 0; k0 < 128; k0 += 32) {
#pragma unroll
        for (int p = 0; p < 2; p++) {
            int rr = r + p * 32;
            float4 v = *(const float4*)&x[(size_t)(row0 + rr) * 128 + k0 + seg * 4];
            xs[rr][seg * 4 + 0] = v.x; xs[rr][seg * 4 + 1] = v.y;
            xs[rr][seg * 4 + 2] = v.z; xs[rr][seg * 4 + 3] = v.w;
        }
        for (int idx = tid; idx < 32 * 128 / 4; idx += 256)
            *(float4*)(&Ws[0][0] + idx * 4) = *(const float4*)&W[(size_t)k0 * 128 + idx * 4];
        __syncthreads();
#pragma unroll 8
        for (int kk = 0; kk < 32; kk++) {
            float a0 = xs[iBase + 0][kk], a1 = xs[iBase + 1][kk];
            float a2 = xs[iBase + 2][kk], a3 = xs[iBase + 3][kk];
            float bv[8];
            *(float4*)&bv[0] = *(const float4*)&Ws[kk][oBase];
            *(float4*)&bv[4] = *(const float4*)&Ws[kk][oBase + 4];
#pragma unroll
            for (int c = 0; c < 8; c++) {
                acc[0][c] += a0 * bv[c];
                acc[1][c] += a1 * bv[c];
                acc[2][c] += a2 * bv[c];
                acc[3][c] += a3 * bv[c];
            }
        }
        __syncthreads();
    }
#pragma unroll
    for (int a = 0; a < 4; a++) {
        float* dst = &g_h[(size_t)(row0 + iBase + a) * 128 + oBase];
        *(float4*)&dst[0] = make_float4(acc[a][0], acc[a][1], acc[a][2], acc[a][3]);
        *(float4*)&dst[4] = make_float4(acc[a][4], acc[a][5], acc[a][6], acc[a][7]);
    }
}

// ---------------------------------------------------------------------------
// K2: s_src = h @ a[:128], s_dst = h @ a[128:]   (one warp per row)
// ---------------------------------------------------------------------------
__global__ __launch_bounds__(256) void k2_s(const float* __restrict__ a) {
    const int warp = threadIdx.x >> 5, lane = threadIdx.x & 31;
    const int row = blockIdx.x * 8 + warp;
    const float* h = &g_h[(size_t)row * 128];
    float s1 = 0.f, s2 = 0.f;
#pragma unroll
    for (int t = 0; t < 4; t++) {
        float hv = h[lane + 32 * t];
        s1 += hv * a[lane + 32 * t];
        s2 += hv * a[128 + lane + 32 * t];
    }
#pragma unroll
    for (int off = 16; off > 0; off >>= 1) {
        s1 += __shfl_xor_sync(0xffffffffu, s1, off);
        s2 += __shfl_xor_sync(0xffffffffu, s2, off);
    }
    if (lane == 0) { g_ssrc[row] = s1; g_sdst[row] = s2; }
}

// ---------------------------------------------------------------------------
// K3: sort s_dst per batch by rank counting (deterministic total order)
// ---------------------------------------------------------------------------
__global__ __launch_bounds__(128) void k3_sort() {
    __shared__ float s[2048];
    const int b = blockIdx.y;
    const int tid = threadIdx.x;
    for (int idx = tid; idx < 2048; idx += 128) s[idx] = g_sdst[b * 2048 + idx];
    __syncthreads();
    const int j = blockIdx.x * 128 + tid;
    const float my = s[j];
    int rank = 0;
    for (int q = 0; q < 2048; q++) {
        float o = s[q];
        rank += (o < my) || (o == my && q < j);
    }
    const int base = b * 2048;
    g_v[base + rank]   = my;
    g_perm[base + rank] = j;
    g_w1[base + rank]  = expf(my);
    g_w02[base + rank] = expf(SLOPE * my);
}

// ---------------------------------------------------------------------------
// K4: fp64 chunked scan -> suf1[k][o] = sum_{r>=k} e^{v_r} h[perm(r)][o]
//                           pre02[k][o] = sum_{r<k}  e^{0.2 v_r} h[perm(r)][o]
// grid (4, 8): 32 o's per block, 16 chunks of 128
// ---------------------------------------------------------------------------
__global__ __launch_bounds__(512) void k4_scanE() {
    __shared__ double cs1[16][33], cs02[16][33];
    __shared__ double off1[16][32], off02[16][32];
    __shared__ double tot1s[32], tot02s[32];
    const int b = blockIdx.y;
    const int ol = threadIdx.x & 31;
    const int o = blockIdx.x * 32 + ol;
    const int c = threadIdx.x >> 5;
    const int base = b * 2048;
    const int r0 = c * 128;

    double a1 = 0.0, a02 = 0.0;
    for (int r2 = r0; r2 < r0 + 128; r2++) {
        int j = g_perm[base + r2];
        float hv = g_h[((size_t)base + j) * 128 + o];
        a1  += (double)g_w1[base + r2]  * hv;
        a02 += (double)g_w02[base + r2] * hv;
    }
    cs1[c][ol] = a1; cs02[c][ol] = a02;
    __syncthreads();
    if (c == 0) {
        double r1 = 0.0, rr2 = 0.0;
        for (int q = 0; q < 16; q++) {
            off1[q][ol] = r1;  r1  += cs1[q][ol];
            off02[q][ol] = rr2; rr2 += cs02[q][ol];
        }
        tot1s[ol] = r1; tot02s[ol] = rr2;
    }
    __syncthreads();
    double run1 = off1[c][ol], run02 = off02[c][ol];
    const double tot1 = tot1s[ol];
    const size_t tbase = ((size_t)b * 2049) * 128 + o;
    for (int r2 = r0; r2 < r0 + 128; r2++) {
        int j = g_perm[base + r2];
        float hv = g_h[((size_t)base + j) * 128 + o];
        g_suf1[tbase + (size_t)r2 * 128]  = (float)(tot1 - run1);
        run1 += (double)g_w1[base + r2] * hv;
        g_pre02[tbase + (size_t)r2 * 128] = (float)run02;
        run02 += (double)g_w02[base + r2] * hv;
    }
    if (c == 15) {
        g_suf1[tbase + (size_t)2048 * 128]  = 0.f;
        g_pre02[tbase + (size_t)2048 * 128] = (float)run02;
    }
}

// ---------------------------------------------------------------------------
// K4b: same scan for the softmax denominators (no h)
// ---------------------------------------------------------------------------
__global__ __launch_bounds__(32) void k4b_scanD() {
    __shared__ double cs1[16], cs02[16], off1[16], off02[16], tot[2];
    const int b = blockIdx.x;
    const int c = threadIdx.x;
    const int base = b * 2048;
    if (c < 16) {
        double a1 = 0.0, a02 = 0.0;
        for (int r = c * 128; r < c * 128 + 128; r++) {
            a1 += (double)g_w1[base + r]; a02 += (double)g_w02[base + r];
        }
        cs1[c] = a1; cs02[c] = a02;
    }
    __syncthreads();
    if (c == 0) {
        double r1 = 0.0, r2 = 0.0;
        for (int q = 0; q < 16; q++) {
            off1[q] = r1; r1 += cs1[q];
            off02[q] = r2; r2 += cs02[q];
        }
        tot[0] = r1; tot[1] = r2;
    }
    __syncthreads();
    if (c < 16) {
        double run1 = off1[c], run02 = off02[c], t1 = tot[0];
        const size_t tb = (size_t)b * 2049;
        for (int r = c * 128; r < c * 128 + 128; r++) {
            g_sufD1[tb + r] = (float)(t1 - run1);
            run1 += (double)g_w1[base + r];
            g_preD02[tb + r] = (float)run02;
            run02 += (double)g_w02[base + r];
        }
        if (c == 15) { g_sufD1[tb + 2048] = 0.f; g_preD02[tb + 2048] = (float)run02; }
    }
}

// ---------------------------------------------------------------------------
// K5: out = lrelu( adj@h  +  attention-epilogue )
// grid (16, 8): 128x128 output tile per block, 8x8 register micro-tile
// ---------------------------------------------------------------------------
__global__ __launch_bounds__(256) void k5_main(const float* __restrict__ adj,
                                               float* __restrict__ out) {
    __shared__ float vS[2048];
    __shared__ float adjS[32][132];   // transposed: [k][i]
    __shared__ float hS[32][128];
    __shared__ float e1S[128], e02S[128], dinvS[128];
    __shared__ int kS[128];
    const int tid = threadIdx.x;
    const int b = blockIdx.y;
    const int i0 = blockIdx.x * 128;

    for (int idx = tid; idx < 2048; idx += 256) vS[idx] = g_v[b * 2048 + idx];
    __syncthreads();
    if (tid < 128) {
        float si = g_ssrc[b * 2048 + i0 + tid];
        float target = -si;
        int lo = 0, hi = 2048;
        while (lo < hi) { int mid = (lo + hi) >> 1; if (vS[mid] < target) lo = mid + 1; else hi = mid; }
        float e1 = expf(si), e02 = expf(SLOPE * si);
        float Dv = e1 * g_sufD1[(size_t)b * 2049 + lo] + e02 * g_preD02[(size_t)b * 2049 + lo];
        kS[tid] = lo; e1S[tid] = e1; e02S[tid] = e02; dinvS[tid] = 1.0f / Dv;
    }
    __syncthreads();

    const int ig = tid >> 4, og = tid & 15;
    const int iBase = ig * 8, oBase = og * 8;
    float acc[8][8];
#pragma unroll
    for (int a = 0; a < 8; a++)
#pragma unroll
        for (int c = 0; c < 8; c++) acc[a][c] = 0.f;

    const float* adjBase = adj + ((size_t)b * 2048 + i0) * 2048;
    const int seg = tid & 7, irow = tid >> 3;   // 0..31

    for (int jt = 0; jt < 2048; jt += 32) {
#pragma unroll
        for (int p = 0; p < 4; p++) {
            int i = irow + p * 32;
            float4 v = *(const float4*)&adjBase[(size_t)i * 2048 + jt + seg * 4];
            adjS[seg * 4 + 0][i] = v.x; adjS[seg * 4 + 1][i] = v.y;
            adjS[seg * 4 + 2][i] = v.z; adjS[seg * 4 + 3][i] = v.w;
        }
        const float* hP = &g_h[((size_t)b * 2048 + jt) * 128];
        for (int idx = tid; idx < 32 * 128 / 4; idx += 256)
            *(float4*)(&hS[0][0] + idx * 4) = *(const float4*)&hP[idx * 4];
        __syncthreads();
#pragma unroll 8
        for (int kk = 0; kk < 32; kk++) {
            float aR[8], bR[8];
            *(float4*)&aR[0] = *(const float4*)&adjS[kk][iBase];
            *(float4*)&aR[4] = *(const float4*)&adjS[kk][iBase + 4];
            *(float4*)&bR[0] = *(const float4*)&hS[kk][oBase];
            *(float4*)&bR[4] = *(const float4*)&hS[kk][oBase + 4];
#pragma unroll
            for (int a = 0; a < 8; a++)
#pragma unroll
                for (int c = 0; c < 8; c++)
                    acc[a][c] += aR[a] * bR[c];
        }
        __syncthreads();
    }

    // epilogue: attention lookup + final leaky-relu
#pragma unroll
    for (int a = 0; a < 8; a++) {
        int il = iBase + a;
        int k = kS[il];
        float e1 = e1S[il], e02 = e02S[il], dinv = dinvS[il];
        const float* suf = &g_suf1[((size_t)b * 2049 + k) * 128 + oBase];
        const float* pre = &g_pre02[((size_t)b * 2049 + k) * 128 + oBase];
        float res[8];
#pragma unroll
        for (int c = 0; c < 8; c++) {
            float attn = (e1 * suf[c] + e02 * pre[c]) * dinv;
            float val = acc[a][c] + attn;
            res[c] = val >= 0.f ? val : SLOPE * val;
        }
        float* dst = &out[((size_t)b * 2048 + i0 + il) * 128 + oBase];
        *(float4*)&dst[0] = make_float4(res[0], res[1], res[2], res[3]);
        *(float4*)&dst[4] = make_float4(res[4], res[5], res[6], res[7]);
    }
}

// ---------------------------------------------------------------------------
extern "C" void kernel_launch(void* const* d_in, const int* in_sizes, int n_in,
                              void* d_out, int out_size) {
    const float* x   = (const float*)d_in[0];
    const float* adj = (const float*)d_in[1];
    const float* W   = (const float*)d_in[2];
    const float* a   = (const float*)d_in[3];
    float* out = (float*)d_out;

    k1_xw<<<256, 256>>>(x, W);
    k2_s<<<2048, 256>>>(a);
    k3_sort<<<dim3(16, 8), 128>>>();
    k4_scanE<<<dim3(4, 8), 512>>>();
    k4b_scanD<<<8, 32>>>();
    k5_main<<<dim3(16, 8), 256>>>(adj, out);
}

// round 4
// speedup vs baseline: 1.9934x; 1.9934x over previous
#include <cuda_runtime.h>
#include <cuda_bf16.h>
#include <math.h>
#include <stdint.h>

#define SLOPE 0.2f

// Shapes fixed: B=8, N=2048, D=128.
__device__ float g_h[8 * 2048 * 128];           // h = x @ W (fp32)
__device__ __nv_bfloat16 g_hT1[8 * 128 * 2048]; // hi bf16 of h, transposed [b][o][j]
__device__ __nv_bfloat16 g_hT2[8 * 128 * 2048]; // lo bf16 residual
__device__ float g_ssrc[8 * 2048];
__device__ float g_sdst[8 * 2048];
__device__ float g_v[8 * 2048];
__device__ int   g_perm[8 * 2048];
__device__ float g_w1[8 * 2048];
__device__ float g_w02[8 * 2048];
__device__ float g_suf1[8 * 2049 * 128];
__device__ float g_pre02[8 * 2049 * 128];
__device__ float g_sufD1[8 * 2049];
__device__ float g_preD02[8 * 2049];

// ---------------------------------------------------------------------------
// helpers (all sm_80-era: ldmatrix / cp.async / mma.sync — no 'a'-gated instrs)
// ---------------------------------------------------------------------------
__device__ __forceinline__ uint32_t smem_u32(const void* p) {
    uint32_t a;
    asm("{ .reg .u64 t; cvta.to.shared.u64 t, %1; cvt.u32.u64 %0, t; }" : "=r"(a) : "l"(p));
    return a;
}
__device__ __forceinline__ void ldmx4(uint32_t* r, uint32_t addr) {
    asm volatile("ldmatrix.sync.aligned.m8n8.x4.shared.b16 {%0,%1,%2,%3}, [%4];"
                 : "=r"(r[0]), "=r"(r[1]), "=r"(r[2]), "=r"(r[3]) : "r"(addr));
}
__device__ __forceinline__ void mma16816(float* d, const uint32_t* a, const uint32_t* b) {
    asm volatile(
        "mma.sync.aligned.m16n8k16.row.col.f32.bf16.bf16.f32 "
        "{%0,%1,%2,%3}, {%4,%5,%6,%7}, {%8,%9}, {%0,%1,%2,%3};"
        : "+f"(d[0]), "+f"(d[1]), "+f"(d[2]), "+f"(d[3])
        : "r"(a[0]), "r"(a[1]), "r"(a[2]), "r"(a[3]), "r"(b[0]), "r"(b[1]));
}
__device__ __forceinline__ void cp16(uint32_t dst, const void* src) {
    asm volatile("cp.async.cg.shared.global [%0], [%1], 16;" :: "r"(dst), "l"(src));
}
#define CP_COMMIT() asm volatile("cp.async.commit_group;" ::: "memory")
#define CP_WAIT0()  asm volatile("cp.async.wait_group 0;" ::: "memory")

__device__ __forceinline__ uint32_t cvt2bf(float hi, float lo) {
    uint32_t r;
    asm("cvt.rn.bf16x2.f32 %0, %1, %2;" : "=r"(r) : "f"(hi), "f"(lo));
    return r;
}
__device__ __forceinline__ void sts64(uint32_t a, uint32_t x, uint32_t y) {
    asm volatile("st.shared.v2.b32 [%0], {%1,%2};" :: "r"(a), "r"(x), "r"(y) : "memory");
}

// ---------------------------------------------------------------------------
// K1: h = x @ W
// ---------------------------------------------------------------------------
__global__ __launch_bounds__(256) void k1_xw(const float* __restrict__ x,
                                             const float* __restrict__ W) {
    __shared__ float xs[64][33];
    __shared__ float Ws[32][128];
    const int tid = threadIdx.x;
    const int row0 = blockIdx.x * 64;
    const int ig = tid >> 4, og = tid & 15;
    const int iBase = ig * 4, oBase = og * 8;
    float acc[4][8];
#pragma unroll
    for (int a = 0; a < 4; a++)
#pragma unroll
        for (int c = 0; c < 8; c++) acc[a][c] = 0.f;

    const int seg = tid & 7, r = tid >> 3;
    for (int k0 = 0; k0 < 128; k0 += 32) {
#pragma unroll
        for (int p = 0; p < 2; p++) {
            int rr = r + p * 32;
            float4 v = *(const float4*)&x[(size_t)(row0 + rr) * 128 + k0 + seg * 4];
            xs[rr][seg * 4 + 0] = v.x; xs[rr][seg * 4 + 1] = v.y;
            xs[rr][seg * 4 + 2] = v.z; xs[rr][seg * 4 + 3] = v.w;
        }
        for (int idx = tid; idx < 32 * 128 / 4; idx += 256)
            *(float4*)(&Ws[0][0] + idx * 4) = *(const float4*)&W[(size_t)k0 * 128 + idx * 4];
        __syncthreads();
#pragma unroll 8
        for (int kk = 0; kk < 32; kk++) {
            float a0 = xs[iBase + 0][kk], a1 = xs[iBase + 1][kk];
            float a2 = xs[iBase + 2][kk], a3 = xs[iBase + 3][kk];
            float bv[8];
            *(float4*)&bv[0] = *(const float4*)&Ws[kk][oBase];
            *(float4*)&bv[4] = *(const float4*)&Ws[kk][oBase + 4];
#pragma unroll
            for (int c = 0; c < 8; c++) {
                acc[0][c] += a0 * bv[c];
                acc[1][c] += a1 * bv[c];
                acc[2][c] += a2 * bv[c];
                acc[3][c] += a3 * bv[c];
            }
        }
        __syncthreads();
    }
#pragma unroll
    for (int a = 0; a < 4; a++) {
        float* dst = &g_h[(size_t)(row0 + iBase + a) * 128 + oBase];
        *(float4*)&dst[0] = make_float4(acc[a][0], acc[a][1], acc[a][2], acc[a][3]);
        *(float4*)&dst[4] = make_float4(acc[a][4], acc[a][5], acc[a][6], acc[a][7]);
    }
}

// ---------------------------------------------------------------------------
// K1b: transpose h -> [b][o][j], split into bf16 hi/lo
// ---------------------------------------------------------------------------
__global__ __launch_bounds__(256) void k1b_split() {
    __shared__ float t[32][33];
    const int b = blockIdx.z;
    const int j0 = blockIdx.x * 32, o0 = blockIdx.y * 32;
    const int tx = threadIdx.x, ty = threadIdx.y;  // 32 x 8
#pragma unroll
    for (int r = 0; r < 32; r += 8)
        t[ty + r][tx] = g_h[((size_t)b * 2048 + j0 + ty + r) * 128 + o0 + tx];
    __syncthreads();
#pragma unroll
    for (int r = 0; r < 32; r += 8) {
        float v = t[tx][ty + r];
        __nv_bfloat16 h1 = __float2bfloat16_rn(v);
        float res = v - __bfloat162float(h1);
        size_t idx = ((size_t)b * 128 + o0 + ty + r) * 2048 + j0 + tx;
        g_hT1[idx] = h1;
        g_hT2[idx] = __float2bfloat16_rn(res);
    }
}

// ---------------------------------------------------------------------------
// K2: s_src / s_dst
// ---------------------------------------------------------------------------
__global__ __launch_bounds__(256) void k2_s(const float* __restrict__ a) {
    const int warp = threadIdx.x >> 5, lane = threadIdx.x & 31;
    const int row = blockIdx.x * 8 + warp;
    const float* h = &g_h[(size_t)row * 128];
    float s1 = 0.f, s2 = 0.f;
#pragma unroll
    for (int t = 0; t < 4; t++) {
        float hv = h[lane + 32 * t];
        s1 += hv * a[lane + 32 * t];
        s2 += hv * a[128 + lane + 32 * t];
    }
#pragma unroll
    for (int off = 16; off > 0; off >>= 1) {
        s1 += __shfl_xor_sync(0xffffffffu, s1, off);
        s2 += __shfl_xor_sync(0xffffffffu, s2, off);
    }
    if (lane == 0) { g_ssrc[row] = s1; g_sdst[row] = s2; }
}

// ---------------------------------------------------------------------------
// K3: rank sort of s_dst per batch
// ---------------------------------------------------------------------------
__global__ __launch_bounds__(128) void k3_sort() {
    __shared__ float s[2048];
    const int b = blockIdx.y;
    const int tid = threadIdx.x;
    for (int idx = tid; idx < 2048; idx += 128) s[idx] = g_sdst[b * 2048 + idx];
    __syncthreads();
    const int j = blockIdx.x * 128 + tid;
    const float my = s[j];
    int rank = 0;
#pragma unroll 8
    for (int q = 0; q < 2048; q++) {
        float o = s[q];
        rank += (o < my) || (o == my && q < j);
    }
    const int base = b * 2048;
    g_v[base + rank]    = my;
    g_perm[base + rank] = j;
    g_w1[base + rank]   = expf(my);
    g_w02[base + rank]  = expf(SLOPE * my);
}

// ---------------------------------------------------------------------------
// K4: fp32 chunked scans for numerator tables (grid (4,8), 1024 thr)
// ---------------------------------------------------------------------------
__global__ __launch_bounds__(1024) void k4_scanE() {
    __shared__ float cs1[32][33], cs02[32][33];
    __shared__ float off1A[32][32], off02A[32][32];
    __shared__ float tot1s[32];
    const int b = blockIdx.y;
    const int ol = threadIdx.x & 31;
    const int o = blockIdx.x * 32 + ol;
    const int c = threadIdx.x >> 5;
    const int base = b * 2048;
    const int r0 = c * 64;

    float a1 = 0.f, a02 = 0.f;
    for (int r = r0; r < r0 + 64; r++) {
        int j = g_perm[base + r];
        float hv = g_h[((size_t)(base + j)) * 128 + o];
        a1  += g_w1[base + r]  * hv;
        a02 += g_w02[base + r] * hv;
    }
    cs1[c][ol] = a1; cs02[c][ol] = a02;
    __syncthreads();
    if (c == 0) {
        float r1 = 0.f, r2 = 0.f;
        for (int q = 0; q < 32; q++) {
            off1A[q][ol] = r1;  r1 += cs1[q][ol];
            off02A[q][ol] = r2; r2 += cs02[q][ol];
        }
        tot1s[ol] = r1;
    }
    __syncthreads();
    float run1 = off1A[c][ol], run02 = off02A[c][ol];
    const float tot1 = tot1s[ol];
    const size_t tbase = ((size_t)b * 2049) * 128 + o;
    for (int r = r0; r < r0 + 64; r++) {
        int j = g_perm[base + r];
        float hv = g_h[((size_t)(base + j)) * 128 + o];
        g_suf1[tbase + (size_t)r * 128]  = tot1 - run1;
        run1 += g_w1[base + r] * hv;
        g_pre02[tbase + (size_t)r * 128] = run02;
        run02 += g_w02[base + r] * hv;
    }
    if (c == 31) {
        g_suf1[tbase + (size_t)2048 * 128]  = 0.f;
        g_pre02[tbase + (size_t)2048 * 128] = run02;
    }
}

// K4b: denominators (tiny, fp64)
__global__ __launch_bounds__(32) void k4b_scanD() {
    __shared__ double cs1[16], cs02[16], off1[16], off02[16], tot[2];
    const int b = blockIdx.x;
    const int c = threadIdx.x;
    const int base = b * 2048;
    if (c < 16) {
        double a1 = 0.0, a02 = 0.0;
        for (int r = c * 128; r < c * 128 + 128; r++) {
            a1 += (double)g_w1[base + r]; a02 += (double)g_w02[base + r];
        }
        cs1[c] = a1; cs02[c] = a02;
    }
    __syncthreads();
    if (c == 0) {
        double r1 = 0.0, r2 = 0.0;
        for (int q = 0; q < 16; q++) {
            off1[q] = r1; r1 += cs1[q];
            off02[q] = r2; r2 += cs02[q];
        }
        tot[0] = r1; tot[1] = r2;
    }
    __syncthreads();
    if (c < 16) {
        double run1 = off1[c], run02 = off02[c], t1 = tot[0];
        const size_t tb = (size_t)b * 2049;
        for (int r = c * 128; r < c * 128 + 128; r++) {
            g_sufD1[tb + r] = (float)(t1 - run1);
            run1 += (double)g_w1[base + r];
            g_preD02[tb + r] = (float)run02;
            run02 += (double)g_w02[base + r];
        }
        if (c == 15) { g_sufD1[tb + 2048] = 0.f; g_preD02[tb + 2048] = (float)run02; }
    }
}

// ---------------------------------------------------------------------------
// K5: mma.sync bf16 3-term split GEMM (adj@h) + attention epilogue + lrelu
// CTA tile 128(i) x 128(o), K=2048 in 32 chunks of 64. 8 warps = 2(i) x 4(o),
// warp tile 64x32. SMEM tiles [128][72] bf16 padded (144B rows, ldmatrix
// conflict-free). 2-stage pipeline: cp.async for B (pre-split h), LDG+convert
// for A (adj split in registers).
// ---------------------------------------------------------------------------
#define STG_BYTES 73728u           // 4 tiles x 128 x 144B
#define OFF_AHI 0u
#define OFF_ALO 18432u
#define OFF_BHI 36864u
#define OFF_BLO 55296u
#define K5_SMEM (2 * STG_BYTES)

__global__ __launch_bounds__(256) void k5_main(const float* __restrict__ adj,
                                               float* __restrict__ out) {
    extern __shared__ __align__(128) char dsm[];
    __shared__ int kS[128];
    __shared__ float e1S[128], e02S[128], dinvS[128];
    const uint32_t sb = smem_u32(dsm);
    const int tid = threadIdx.x;
    const int b = blockIdx.y;
    const int i0 = blockIdx.x * 128;

    // --- binary-search setup (uses dynamic smem as temp before tiles) ---
    {
        float* vS = (float*)dsm;
        for (int idx = tid; idx < 2048; idx += 256) vS[idx] = g_v[b * 2048 + idx];
        __syncthreads();
        if (tid < 128) {
            float si = g_ssrc[b * 2048 + i0 + tid];
            float target = -si;
            int lo = 0, hi = 2048;
            while (lo < hi) { int mid = (lo + hi) >> 1; if (vS[mid] < target) lo = mid + 1; else hi = mid; }
            float e1 = expf(si), e02 = expf(SLOPE * si);
            float Dv = e1 * g_sufD1[(size_t)b * 2049 + lo] + e02 * g_preD02[(size_t)b * 2049 + lo];
            kS[tid] = lo; e1S[tid] = e1; e02S[tid] = e02; dinvS[tid] = 1.0f / Dv;
        }
        __syncthreads();
    }

    // loader mapping: row = tid>>1 (0..127), half = tid&1 (32-col subchunk)
    const int row = tid >> 1, half = tid & 1;
    const float* aRow = adj + ((size_t)(b * 2048 + i0 + row)) * 2048 + half * 32;
    const __nv_bfloat16* b1Row = g_hT1 + ((size_t)(b * 128 + row)) * 2048 + half * 32;
    const __nv_bfloat16* b2Row = g_hT2 + ((size_t)(b * 128 + row)) * 2048 + half * 32;
    const uint32_t stsBase = (uint32_t)row * 144 + (uint32_t)half * 64;

    // compute mapping: warp -> (wi in {0,1}, wo in {0..3})
    const int warp = tid >> 5, lane = tid & 31;
    const int wi = warp & 1, wo = warp >> 1;
    const int obase = wo * 32;
    // ldmatrix lane address components
    const uint32_t aLane = (uint32_t)(wi * 64 + (lane & 15)) * 144 + ((lane >> 4) << 4);
    const uint32_t bLane = (uint32_t)(obase + (lane & 7) + ((lane & 16) >> 1)) * 144 + ((lane & 8) << 1);

    float acc[4][4][4];
#pragma unroll
    for (int mf = 0; mf < 4; mf++)
#pragma unroll
        for (int nf = 0; nf < 4; nf++)
#pragma unroll
            for (int e = 0; e < 4; e++) acc[mf][nf][e] = 0.f;

    // ---- prologue: stage 0 <- chunk 0 ----
    {
#pragma unroll
        for (int p = 0; p < 4; p++) {
            cp16(sb + OFF_BHI + stsBase + p * 16, b1Row + p * 8);
            cp16(sb + OFF_BLO + stsBase + p * 16, b2Row + p * 8);
        }
        CP_COMMIT();
#pragma unroll
        for (int p = 0; p < 8; p++) {
            float4 u = *(const float4*)(aRow + p * 4);
            uint32_t hi = cvt2bf(u.y, u.x);
            uint32_t hj = cvt2bf(u.w, u.z);
            float l0 = u.x - __uint_as_float(hi << 16);
            float l1 = u.y - __uint_as_float(hi & 0xffff0000u);
            float l2 = u.z - __uint_as_float(hj << 16);
            float l3 = u.w - __uint_as_float(hj & 0xffff0000u);
            sts64(sb + OFF_AHI + stsBase + p * 8, hi, hj);
            sts64(sb + OFF_ALO + stsBase + p * 8, cvt2bf(l1, l0), cvt2bf(l3, l2));
        }
        CP_WAIT0();
        __syncthreads();
    }

    for (int c = 0; c < 32; c++) {
        const uint32_t sCur = sb + (c & 1 ? STG_BYTES : 0u);
        const uint32_t sNxt = sb + (c & 1 ? 0u : STG_BYTES);
        const int j1 = (c + 1) * 64;
        float4 fA[8];
        if (c < 31) {
#pragma unroll
            for (int p = 0; p < 4; p++) {
                cp16(sNxt + OFF_BHI + stsBase + p * 16, b1Row + j1 + p * 8);
                cp16(sNxt + OFF_BLO + stsBase + p * 16, b2Row + j1 + p * 8);
            }
            CP_COMMIT();
#pragma unroll
            for (int p = 0; p < 8; p++) fA[p] = *(const float4*)(aRow + j1 + p * 4);
        }
        // ---- compute current chunk: 4 k16 steps ----
#pragma unroll
        for (int kk = 0; kk < 4; kk++) {
            uint32_t aH[4][4], aL[4][4], bH[8], bL[8];
            const uint32_t aAddr = sCur + aLane + kk * 32;
            const uint32_t bAddr = sCur + bLane + kk * 32;
#pragma unroll
            for (int mf = 0; mf < 4; mf++) {
                ldmx4(aH[mf], aAddr + OFF_AHI + mf * (16 * 144));
                ldmx4(aL[mf], aAddr + OFF_ALO + mf * (16 * 144));
            }
            ldmx4(&bH[0], bAddr + OFF_BHI);
            ldmx4(&bH[4], bAddr + OFF_BHI + 16 * 144);
            ldmx4(&bL[0], bAddr + OFF_BLO);
            ldmx4(&bL[4], bAddr + OFF_BLO + 16 * 144);
#pragma unroll
            for (int mf = 0; mf < 4; mf++)
#pragma unroll
                for (int nf = 0; nf < 4; nf++) {
                    mma16816(acc[mf][nf], aH[mf], &bH[nf * 2]);
                    mma16816(acc[mf][nf], aH[mf], &bL[nf * 2]);
                    mma16816(acc[mf][nf], aL[mf], &bH[nf * 2]);
                }
        }
        if (c < 31) {
#pragma unroll
            for (int p = 0; p < 8; p++) {
                float4 u = fA[p];
                uint32_t hi = cvt2bf(u.y, u.x);
                uint32_t hj = cvt2bf(u.w, u.z);
                float l0 = u.x - __uint_as_float(hi << 16);
                float l1 = u.y - __uint_as_float(hi & 0xffff0000u);
                float l2 = u.z - __uint_as_float(hj << 16);
                float l3 = u.w - __uint_as_float(hj & 0xffff0000u);
                sts64(sNxt + OFF_AHI + stsBase + p * 8, hi, hj);
                sts64(sNxt + OFF_ALO + stsBase + p * 8, cvt2bf(l1, l0), cvt2bf(l3, l2));
            }
        }
        CP_WAIT0();
        __syncthreads();
    }

    // ---- epilogue: attention lookup + lrelu + store ----
#pragma unroll
    for (int mf = 0; mf < 4; mf++) {
        const int rl0 = wi * 64 + mf * 16 + (lane >> 2);
#pragma unroll
        for (int hh = 0; hh < 2; hh++) {
            const int rl = rl0 + hh * 8;
            const int k = kS[rl];
            const float e1 = e1S[rl], e02 = e02S[rl], dinv = dinvS[rl];
            const float* suf = &g_suf1[((size_t)(b * 2049 + k)) * 128];
            const float* pre = &g_pre02[((size_t)(b * 2049 + k)) * 128];
            float* dst = &out[((size_t)(b * 2048 + i0 + rl)) * 128];
#pragma unroll
            for (int nf = 0; nf < 4; nf++) {
                const int o = obase + nf * 8 + (lane & 3) * 2;
                float2 sf = *(const float2*)&suf[o];
                float2 pf = *(const float2*)&pre[o];
                float v0 = acc[mf][nf][hh * 2 + 0] + (e1 * sf.x + e02 * pf.x) * dinv;
                float v1 = acc[mf][nf][hh * 2 + 1] + (e1 * sf.y + e02 * pf.y) * dinv;
                float2 r;
                r.x = v0 >= 0.f ? v0 : SLOPE * v0;
                r.y = v1 >= 0.f ? v1 : SLOPE * v1;
                *(float2*)&dst[o] = r;
            }
        }
    }
}

// ---------------------------------------------------------------------------
extern "C" void kernel_launch(void* const* d_in, const int* in_sizes, int n_in,
                              void* d_out, int out_size) {
    (void)in_sizes; (void)n_in; (void)out_size;
    const float* x   = (const float*)d_in[0];
    const float* adj = (const float*)d_in[1];
    const float* W   = (const float*)d_in[2];
    const float* a   = (const float*)d_in[3];
    float* out = (float*)d_out;

    cudaFuncSetAttribute(k5_main, cudaFuncAttributeMaxDynamicSharedMemorySize, K5_SMEM);

    k1_xw<<<256, 256>>>(x, W);
    k1b_split<<<dim3(64, 4, 8), dim3(32, 8)>>>();
    k2_s<<<2048, 256>>>(a);
    k3_sort<<<dim3(16, 8), 128>>>();
    k4_scanE<<<dim3(4, 8), 1024>>>();
    k4b_scanD<<<8, 32>>>();
    k5_main<<<dim3(16, 8), 256, K5_SMEM>>>(adj, out);
}